// round 10
// baseline (speedup 1.0000x reference)
#include <cuda_runtime.h>
#include <cuda_fp16.h>
#include <cstdint>
#include <math.h>

#define B_    2
#define N_    2048
#define D_    1024
#define RANK_ 256
#define HEADS_ 16
#define HS_   16
#define DH_   64
#define QKW_  512
#define CW_   1536           // merged GEMM output width (512 qk + 1024 v)
#define NT_   96             // GEMM N-tile
#define SCALE_ 0.25f
#define MROWS (B_*N_)        // 4096

// ---------------- device scratch (no allocation allowed) --------------------
__device__ __half g_qkh[MROWS*QKW_];      // fp16 qk pre-normalization
__device__ __half g_x16[MROWS*D_];        // x fp16
__device__ __half g_wh[CW_*D_];           // [Wqk;Wv] fp16
__device__ __half g_vh[MROWS*D_];         // v fp16
// q (scaled) and k fp16, [b,h,n,hs] layout
__device__ __half g_q16[B_*HEADS_*N_*HS_];
__device__ __half g_k16[B_*HEADS_*N_*HS_];

// ---------------- PTX helpers (sm_100-baseline safe) ------------------------
__device__ __forceinline__ uint32_t smem_u32(const void* p) {
    uint32_t a;
    asm("{ .reg .u64 t; cvta.to.shared.u64 t, %1; cvt.u32.u64 %0, t; }" : "=r"(a) : "l"(p));
    return a;
}
__device__ __forceinline__ void cp_async16(uint32_t dst, const void* src) {
    asm volatile("cp.async.cg.shared.global [%0], [%1], 16;" :: "r"(dst), "l"(src) : "memory");
}
#define CP_COMMIT() asm volatile("cp.async.commit_group;" ::: "memory")
#define CP_WAIT(n)  asm volatile("cp.async.wait_group %0;" :: "n"(n) : "memory")

__device__ __forceinline__ void ldsm4(uint32_t* r, uint32_t addr) {
    asm volatile("ldmatrix.sync.aligned.m8n8.x4.shared.b16 {%0,%1,%2,%3}, [%4];"
                 : "=r"(r[0]), "=r"(r[1]), "=r"(r[2]), "=r"(r[3]) : "r"(addr));
}
__device__ __forceinline__ void ldsm4t(uint32_t* r, uint32_t addr) {
    asm volatile("ldmatrix.sync.aligned.m8n8.x4.trans.shared.b16 {%0,%1,%2,%3}, [%4];"
                 : "=r"(r[0]), "=r"(r[1]), "=r"(r[2]), "=r"(r[3]) : "r"(addr));
}
__device__ __forceinline__ void mma16816(float* d, const uint32_t* a, const uint32_t* b) {
    asm volatile("mma.sync.aligned.m16n8k16.row.col.f32.f16.f16.f32 "
                 "{%0,%1,%2,%3}, {%4,%5,%6,%7}, {%8,%9}, {%0,%1,%2,%3};"
                 : "+f"(d[0]), "+f"(d[1]), "+f"(d[2]), "+f"(d[3])
                 : "r"(a[0]), "r"(a[1]), "r"(a[2]), "r"(a[3]), "r"(b[0]), "r"(b[1]));
}
// packed f32x2 -> f16x2 (lo arg in low half)
#define CVT2PKH(d, lo, hi) asm("cvt.rn.f16x2.f32 %0, %1, %2;" : "=r"(d) : "f"(hi), "f"(lo))

// exp(s) for |s| <= 0.26: Taylor-4, rel err < 1e-5
__device__ __forceinline__ float exp_poly(float s) {
    float p = fmaf(s, 1.f/24.f, 1.f/6.f);
    p = fmaf(s, p, 0.5f);
    p = fmaf(s, p, 1.f);
    p = fmaf(s, p, 1.f);
    return p;
}

// ---------------- merged fp32 -> fp16 conversion (x, Wqk, Wv) ---------------
#define CVT_BLOCKS (4096 + 512 + 1024)
__global__ __launch_bounds__(256) void convert_all(const float* __restrict__ x,
                                                   const float* __restrict__ Wqk,
                                                   const float* __restrict__ Wv)
{
    int bid = blockIdx.x;
    const float* src;
    __half* dst;
    size_t off;
    if (bid < 4096)      { src = x;   dst = g_x16; off = (size_t)bid * 1024; }
    else if (bid < 4608) { src = Wqk; dst = g_wh;  off = (size_t)(bid - 4096) * 1024; }
    else                 { src = Wv;  dst = g_wh + (size_t)QKW_*D_; off = (size_t)(bid - 4608) * 1024; }
    size_t i = off + threadIdx.x * 4;
    float4 v = *(const float4*)(src + i);
    uint32_t h01, h23;
    CVT2PKH(h01, v.x, v.y);
    CVT2PKH(h23, v.z, v.w);
    *(uint2*)(dst + i) = make_uint2(h01, h23);
}

// ---------------- merged mma.sync fp16 GEMM ---------------------------------
#define TILE_PITCH 144                  // 64 halves + 16B pad
#define AT_B   (128 * TILE_PITCH)       // 18432
#define BT_B   (NT_ * TILE_PITCH)       // 13824
#define T_B0   AT_B
#define STAGE_B (AT_B + BT_B)           // 32256
#define GEMM_SMEM (2 * STAGE_B)         // 64512

__global__ __launch_bounds__(384, 2) void gemm_fused(const __half* __restrict__ A16,
                                                     const __half* __restrict__ Wh)
{
    extern __shared__ __align__(128) char smem[];
    const uint32_t sb = smem_u32(smem);

    const int tid = threadIdx.x;
    const int lane = tid & 31, wid = tid >> 5;
    const int wr = wid & 3, wc = wid >> 2;           // 4M x 3N warp grid
    const int row0 = blockIdx.y * 128, col0 = blockIdx.x * NT_;

    const __half* pA = A16 + (size_t)row0 * D_;
    const __half* pB = Wh + (size_t)col0 * D_;
    const int lrow = tid >> 3, lc = tid & 7;         // 48 rows per 384-thread pass

    auto load_stage = [&](int s, int k0) {
        uint32_t dbase = sb + s * STAGE_B;
        #pragma unroll
        for (int it = 0; it < 3; it++) {             // A: 128 rows x 8 chunks
            int row = lrow + it * 48;
            if (it < 2 || row < 128)
                cp_async16(dbase + row * TILE_PITCH + lc * 16,
                           pA + (size_t)row * D_ + k0 + lc * 8);
        }
        #pragma unroll
        for (int it = 0; it < 2; it++) {             // B: 96 rows x 8 chunks
            int row = lrow + it * 48;
            cp_async16(dbase + T_B0 + row * TILE_PITCH + lc * 16,
                       pB + (size_t)row * D_ + k0 + lc * 8);
        }
        CP_COMMIT();
    };

    const uint32_t a_off = (uint32_t)((wr * 32 + (lane & 15)) * TILE_PITCH + ((lane >> 4) << 4));
    const uint32_t b_off = (uint32_t)((wc * 32 + (lane & 7) + ((lane >> 4) << 3)) * TILE_PITCH
                                      + (((lane >> 3) & 1) << 4));

    float acc[2][4][4];
    #pragma unroll
    for (int mt = 0; mt < 2; mt++)
        #pragma unroll
        for (int nt = 0; nt < 4; nt++)
            #pragma unroll
            for (int r = 0; r < 4; r++) acc[mt][nt][r] = 0.f;

    load_stage(0, 0);

    const int NK = D_ / 64;     // 16
    for (int kt = 0; kt < NK; kt++) {
        if (kt + 1 < NK) { load_stage((kt + 1) & 1, (kt + 1) * 64); CP_WAIT(1); }
        else             { CP_WAIT(0); }
        __syncthreads();

        uint32_t stage = sb + (kt & 1) * STAGE_B;
        #pragma unroll
        for (int kk = 0; kk < 4; kk++) {
            uint32_t ko = kk * 32;                  // 16 halves per k-step
            uint32_t ah[2][4];
            #pragma unroll
            for (int mt = 0; mt < 2; mt++)
                ldsm4(ah[mt], stage + a_off + mt * (16 * TILE_PITCH) + ko);
            uint32_t bh[2][4];
            #pragma unroll
            for (int ng = 0; ng < 2; ng++)
                ldsm4(bh[ng], stage + T_B0 + b_off + ng * (16 * TILE_PITCH) + ko);
            #pragma unroll
            for (int mt = 0; mt < 2; mt++)
                #pragma unroll
                for (int ng = 0; ng < 2; ng++)
                    #pragma unroll
                    for (int hf = 0; hf < 2; hf++)
                        mma16816(acc[mt][ng * 2 + hf], ah[mt], &bh[ng][hf * 2]);
        }
        __syncthreads();
    }

    // epilogue: fp16 everywhere; qk vs v routing per 8-col fragment
    #pragma unroll
    for (int mt = 0; mt < 2; mt++) {
        int rbase = row0 + wr * 32 + mt * 16 + (lane >> 2);
        #pragma unroll
        for (int nt = 0; nt < 4; nt++) {
            int colg = col0 + wc * 32 + nt * 8 + (lane & 3) * 2;
            uint32_t p0, p1;
            CVT2PKH(p0, acc[mt][nt][0], acc[mt][nt][1]);
            CVT2PKH(p1, acc[mt][nt][2], acc[mt][nt][3]);
            if (colg < QKW_) {
                *(uint32_t*)(g_qkh + (size_t)rbase * QKW_ + colg)       = p0;
                *(uint32_t*)(g_qkh + (size_t)(rbase + 8) * QKW_ + colg) = p1;
            } else {
                int col = colg - QKW_;
                *(uint32_t*)(g_vh + (size_t)rbase * D_ + col)       = p0;
                *(uint32_t*)(g_vh + (size_t)(rbase + 8) * D_ + col) = p1;
            }
        }
    }
}

// ---------------- L2 normalize + emit fp16 q (scaled), k --------------------
__global__ __launch_bounds__(256) void normalize_qk()
{
    int n = blockIdx.x;
    int b = n >> 11, nn = n & 2047;
    const __half* p = g_qkh + (size_t)n * QKW_;
    int t = threadIdx.x;
    float qv = __half2float(p[t]), kv = __half2float(p[RANK_ + t]);
    float qs = qv*qv, ks = kv*kv;
    #pragma unroll
    for (int o = 16; o; o >>= 1) {
        qs += __shfl_xor_sync(0xffffffffu, qs, o);
        ks += __shfl_xor_sync(0xffffffffu, ks, o);
    }
    __shared__ float sq[8], sk[8];
    if ((t & 31) == 0) { sq[t>>5] = qs; sk[t>>5] = ks; }
    __syncthreads();
    float qn = 0.f, kn = 0.f;
    #pragma unroll
    for (int w = 0; w < 8; w++) { qn += sq[w]; kn += sk[w]; }
    float qo = qv / fmaxf(sqrtf(qn), 1e-6f) * SCALE_;
    float ko = kv / fmaxf(sqrtf(kn), 1e-6f);

    int h = t >> 4, c = t & 15;
    size_t dst = ((size_t)(b*HEADS_ + h) * N_ + nn) * HS_ + c;
    g_q16[dst] = __float2half_rn(qo);
    g_k16[dst] = __float2half_rn(ko);
}

// ---------------- tensor-core causal flash attention ------------------------
// Q,K,V,P fp16. lsum via P@ones MMA. Mask only near-diagonal tiles; skip
// fully-masked tiles per warp.
#define SQ_   0
#define SST_  6144
#define STG_  12288
#define SKH_  0
#define SVH_  3072
#define FLASH_SMEM 30720    // 6144 + 2*12288

__global__ __launch_bounds__(256, 2) void flash_tc(float* __restrict__ out)
{
    extern __shared__ __align__(128) char smem[];
    const uint32_t sb = smem_u32(smem);
    const int tid = threadIdx.x, lane = tid & 31, wid = tid >> 5;
    const int qt = gridDim.x - 1 - blockIdx.x;
    const int h = blockIdx.y, b = blockIdx.z;
    const int q0 = qt * 128;
    const size_t bh = (size_t)(b*HEADS_ + h) * N_;
    const size_t vb = (size_t)b * N_;

    {   // Q: 128 rows x 2 chunks = 256
        int row = tid >> 1, c = tid & 1;
        cp_async16(sb + SQ_ + row * 48 + c * 16,
                   g_q16 + (bh + q0 + row) * HS_ + c * 8);
    }
    CP_COMMIT();

    auto load_kv = [&](int s, int ktile) {
        uint32_t st = sb + SST_ + s * STG_;
        int j0 = ktile * 64;
        if (tid < 128) {   // K: 64 rows x 2 chunks
            int c = tid & 1, row = tid >> 1;
            cp_async16(st + SKH_ + row * 48 + c * 16,
                       g_k16 + (bh + j0 + row) * HS_ + c * 8);
        }
        #pragma unroll
        for (int it = 0; it < 2; it++) {   // V: 64 rows x 8 chunks = 512
            int idx = tid + it * 256;
            int c = idx & 7, row = idx >> 3;
            cp_async16(st + SVH_ + row * 144 + c * 16,
                       g_vh + (vb + j0 + row) * D_ + h * DH_ + c * 8);
        }
        CP_COMMIT();
    };

    load_kv(0, 0);

    uint32_t qa[4];
    float yacc[8][4];
    #pragma unroll
    for (int nt = 0; nt < 8; nt++)
        #pragma unroll
        for (int r = 0; r < 4; r++) yacc[nt][r] = 0.f;
    float lacc[4] = {0.f, 0.f, 0.f, 0.f};          // P@ones accumulator
    const uint32_t ones2[2] = {0x3C003C00u, 0x3C003C00u};

    const int wmin = q0 + wid * 16;                // warp's min q row
    const int r0g = wmin + (lane >> 2);
    const int r1g = r0g + 8;
    const int nkt = 2 * qt + 2;
    const uint32_t qoff = (uint32_t)((wid * 16 + (lane & 15)) * 48 + ((lane >> 4) << 4));
    const uint32_t koff = (uint32_t)((((lane >> 4) << 3) + (lane & 7)) * 48
                                     + (((lane >> 3) & 1) << 4));
    const uint32_t voff = (uint32_t)(((((lane >> 3) & 1) << 3) + (lane & 7)) * 144
                                     + ((lane >> 4) << 4));

    for (int kt = 0; kt < nkt; kt++) {
        if (kt + 1 < nkt) { load_kv((kt + 1) & 1, kt + 1); CP_WAIT(1); }
        else              { CP_WAIT(0); }
        __syncthreads();

        if (kt == 0) ldsm4(qa, sb + SQ_ + qoff);

        const int j0 = kt * 64;
        if (j0 <= wmin + 15) {                     // else: tile fully masked for warp
            uint32_t st = sb + SST_ + (kt & 1) * STG_;
            uint32_t pah[4][4];

            if (j0 + 63 <= wmin) {
                // ---- fast path: no masking anywhere in this tile ----
                #pragma unroll
                for (int ntp = 0; ntp < 4; ntp++) {
                    uint32_t khr[4];
                    ldsm4(khr, st + SKH_ + koff + ntp * (16 * 48));
                    float s0[4] = {0,0,0,0}, s1[4] = {0,0,0,0};
                    mma16816(s0, qa, &khr[0]);
                    mma16816(s1, qa, &khr[2]);
                    #pragma unroll
                    for (int hf = 0; hf < 2; hf++) {
                        float* s = hf ? s1 : s0;
                        float p0 = exp_poly(s[0]), p1 = exp_poly(s[1]);
                        float p2 = exp_poly(s[2]), p3 = exp_poly(s[3]);
                        uint32_t hh01, hh23;
                        CVT2PKH(hh01, p0, p1);
                        CVT2PKH(hh23, p2, p3);
                        pah[ntp][hf * 2]     = hh01;
                        pah[ntp][hf * 2 + 1] = hh23;
                    }
                }
            } else {
                // ---- diagonal tile: per-element causal mask ----
                #pragma unroll
                for (int ntp = 0; ntp < 4; ntp++) {
                    uint32_t khr[4];
                    ldsm4(khr, st + SKH_ + koff + ntp * (16 * 48));
                    float s0[4] = {0,0,0,0}, s1[4] = {0,0,0,0};
                    mma16816(s0, qa, &khr[0]);
                    mma16816(s1, qa, &khr[2]);
                    #pragma unroll
                    for (int hf = 0; hf < 2; hf++) {
                        float* s = hf ? s1 : s0;
                        int c0 = j0 + (ntp * 2 + hf) * 8 + 2 * (lane & 3);
                        float p0 = (c0     <= r0g) ? exp_poly(s[0]) : 0.f;
                        float p1 = (c0 + 1 <= r0g) ? exp_poly(s[1]) : 0.f;
                        float p2 = (c0     <= r1g) ? exp_poly(s[2]) : 0.f;
                        float p3 = (c0 + 1 <= r1g) ? exp_poly(s[3]) : 0.f;
                        uint32_t hh01, hh23;
                        CVT2PKH(hh01, p0, p1);
                        CVT2PKH(hh23, p2, p3);
                        pah[ntp][hf * 2]     = hh01;
                        pah[ntp][hf * 2 + 1] = hh23;
                    }
                }
            }

            // ---- lsum via P @ ones ----
            #pragma unroll
            for (int ks = 0; ks < 4; ks++)
                mma16816(lacc, pah[ks], ones2);

            // ---- P @ V ----
            #pragma unroll
            for (int ks = 0; ks < 4; ks++) {
                #pragma unroll
                for (int dnp = 0; dnp < 4; dnp++) {
                    uint32_t vh4[4];
                    ldsm4t(vh4, st + SVH_ + voff + ks * (16 * 144) + dnp * 32);
                    mma16816(yacc[2*dnp],     pah[ks], &vh4[0]);
                    mma16816(yacc[2*dnp + 1], pah[ks], &vh4[2]);
                }
            }
        }
        __syncthreads();
    }

    // all-ones B makes every accumulator column the row sum: no shuffles needed
    float inv0 = 1.f / fmaxf(lacc[0], 1e-6f);
    float inv1 = 1.f / fmaxf(lacc[2], 1e-6f);

    float* o0 = out + ((size_t)b * N_ + r0g) * D_ + h * DH_ + 2 * (lane & 3);
    #pragma unroll
    for (int nt = 0; nt < 8; nt++) {
        *(float2*)(o0 + nt * 8)           = make_float2(yacc[nt][0] * inv0, yacc[nt][1] * inv0);
        *(float2*)(o0 + nt * 8 + 8 * D_)  = make_float2(yacc[nt][2] * inv1, yacc[nt][3] * inv1);
    }
}

// ----------------------------------------------------------------------------
extern "C" void kernel_launch(void* const* d_in, const int* in_sizes, int n_in,
                              void* d_out, int out_size)
{
    const float* x   = (const float*)d_in[0];
    const float* Wqk = (const float*)d_in[2];
    const float* Wv  = (const float*)d_in[3];
    float* out = (float*)d_out;

    __half *x16, *wh;
    cudaGetSymbolAddress((void**)&x16, g_x16);
    cudaGetSymbolAddress((void**)&wh, g_wh);

    cudaFuncSetAttribute(gemm_fused, cudaFuncAttributeMaxDynamicSharedMemorySize, GEMM_SMEM);
    cudaFuncSetAttribute(flash_tc,   cudaFuncAttributeMaxDynamicSharedMemorySize, FLASH_SMEM);

    convert_all<<<CVT_BLOCKS, 256>>>(x, Wqk, Wv);

    gemm_fused<<<dim3(CW_/NT_, MROWS/128), 384, GEMM_SMEM>>>(x16, wh);

    normalize_qk<<<MROWS, 256>>>();
    flash_tc<<<dim3(N_/128, HEADS_, B_), 256, FLASH_SMEM>>>(out);
}

// round 11
// speedup vs baseline: 1.0658x; 1.0658x over previous
#include <cuda_runtime.h>
#include <cuda_fp16.h>
#include <cstdint>
#include <math.h>

#define B_    2
#define N_    2048
#define D_    1024
#define RANK_ 256
#define HEADS_ 16
#define HS_   16
#define DH_   64
#define QKW_  512
#define CW_   1536           // merged GEMM output width (512 qk + 1024 v)
#define NT_   96             // GEMM N-tile
#define SCALE_ 0.25f
#define MROWS (B_*N_)        // 4096

// ---------------- device scratch (no allocation allowed) --------------------
__device__ __half g_qkh[MROWS*QKW_];      // fp16 qk pre-normalization
__device__ __half g_x16[MROWS*D_];        // x fp16
__device__ __half g_wh[CW_*D_];           // [Wqk;Wv] fp16
__device__ __half g_vh[MROWS*D_];         // v fp16
// q (scaled) and k fp16, [b,h,n,hs] layout
__device__ __half g_q16[B_*HEADS_*N_*HS_];
__device__ __half g_k16[B_*HEADS_*N_*HS_];

// ---------------- PTX helpers (sm_100-baseline safe) ------------------------
__device__ __forceinline__ uint32_t smem_u32(const void* p) {
    uint32_t a;
    asm("{ .reg .u64 t; cvta.to.shared.u64 t, %1; cvt.u32.u64 %0, t; }" : "=r"(a) : "l"(p));
    return a;
}
__device__ __forceinline__ void cp_async16(uint32_t dst, const void* src) {
    asm volatile("cp.async.cg.shared.global [%0], [%1], 16;" :: "r"(dst), "l"(src) : "memory");
}
#define CP_COMMIT() asm volatile("cp.async.commit_group;" ::: "memory")
#define CP_WAIT(n)  asm volatile("cp.async.wait_group %0;" :: "n"(n) : "memory")

__device__ __forceinline__ void ldsm4(uint32_t* r, uint32_t addr) {
    asm volatile("ldmatrix.sync.aligned.m8n8.x4.shared.b16 {%0,%1,%2,%3}, [%4];"
                 : "=r"(r[0]), "=r"(r[1]), "=r"(r[2]), "=r"(r[3]) : "r"(addr));
}
__device__ __forceinline__ void ldsm4t(uint32_t* r, uint32_t addr) {
    asm volatile("ldmatrix.sync.aligned.m8n8.x4.trans.shared.b16 {%0,%1,%2,%3}, [%4];"
                 : "=r"(r[0]), "=r"(r[1]), "=r"(r[2]), "=r"(r[3]) : "r"(addr));
}
__device__ __forceinline__ void mma16816(float* d, const uint32_t* a, const uint32_t* b) {
    asm volatile("mma.sync.aligned.m16n8k16.row.col.f32.f16.f16.f32 "
                 "{%0,%1,%2,%3}, {%4,%5,%6,%7}, {%8,%9}, {%0,%1,%2,%3};"
                 : "+f"(d[0]), "+f"(d[1]), "+f"(d[2]), "+f"(d[3])
                 : "r"(a[0]), "r"(a[1]), "r"(a[2]), "r"(a[3]), "r"(b[0]), "r"(b[1]));
}
// packed f32x2 -> f16x2 (lo arg in low half)
#define CVT2PKH(d, lo, hi) asm("cvt.rn.f16x2.f32 %0, %1, %2;" : "=r"(d) : "f"(hi), "f"(lo))

// exp(s) for |s| <= 0.26: Taylor-4, rel err < 1e-5
__device__ __forceinline__ float exp_poly(float s) {
    float p = fmaf(s, 1.f/24.f, 1.f/6.f);
    p = fmaf(s, p, 0.5f);
    p = fmaf(s, p, 1.f);
    p = fmaf(s, p, 1.f);
    return p;
}

// ---------------- merged fp32 -> fp16 conversion (x, Wqk, Wv) ---------------
#define CVT_BLOCKS (4096 + 512 + 1024)
__global__ __launch_bounds__(256) void convert_all(const float* __restrict__ x,
                                                   const float* __restrict__ Wqk,
                                                   const float* __restrict__ Wv)
{
    int bid = blockIdx.x;
    const float* src;
    __half* dst;
    size_t off;
    if (bid < 4096)      { src = x;   dst = g_x16; off = (size_t)bid * 1024; }
    else if (bid < 4608) { src = Wqk; dst = g_wh;  off = (size_t)(bid - 4096) * 1024; }
    else                 { src = Wv;  dst = g_wh + (size_t)QKW_*D_; off = (size_t)(bid - 4608) * 1024; }
    size_t i = off + threadIdx.x * 4;
    float4 v = *(const float4*)(src + i);
    uint32_t h01, h23;
    CVT2PKH(h01, v.x, v.y);
    CVT2PKH(h23, v.z, v.w);
    *(uint2*)(dst + i) = make_uint2(h01, h23);
}

// ---------------- merged mma.sync fp16 GEMM ---------------------------------
#define TILE_PITCH 144                  // 64 halves + 16B pad
#define AT_B   (128 * TILE_PITCH)       // 18432
#define BT_B   (NT_ * TILE_PITCH)       // 13824
#define T_B0   AT_B
#define STAGE_B (AT_B + BT_B)           // 32256
#define GEMM_SMEM (2 * STAGE_B)         // 64512

__global__ __launch_bounds__(384, 2) void gemm_fused(const __half* __restrict__ A16,
                                                     const __half* __restrict__ Wh)
{
    extern __shared__ __align__(128) char smem[];
    const uint32_t sb = smem_u32(smem);

    const int tid = threadIdx.x;
    const int lane = tid & 31, wid = tid >> 5;
    const int wr = wid & 3, wc = wid >> 2;           // 4M x 3N warp grid
    const int row0 = blockIdx.y * 128, col0 = blockIdx.x * NT_;

    const __half* pA = A16 + (size_t)row0 * D_;
    const __half* pB = Wh + (size_t)col0 * D_;
    const int lrow = tid >> 3, lc = tid & 7;         // 48 rows per 384-thread pass

    auto load_stage = [&](int s, int k0) {
        uint32_t dbase = sb + s * STAGE_B;
        #pragma unroll
        for (int it = 0; it < 3; it++) {             // A: 128 rows x 8 chunks
            int row = lrow + it * 48;
            if (it < 2 || row < 128)
                cp_async16(dbase + row * TILE_PITCH + lc * 16,
                           pA + (size_t)row * D_ + k0 + lc * 8);
        }
        #pragma unroll
        for (int it = 0; it < 2; it++) {             // B: 96 rows x 8 chunks
            int row = lrow + it * 48;
            cp_async16(dbase + T_B0 + row * TILE_PITCH + lc * 16,
                       pB + (size_t)row * D_ + k0 + lc * 8);
        }
        CP_COMMIT();
    };

    const uint32_t a_off = (uint32_t)((wr * 32 + (lane & 15)) * TILE_PITCH + ((lane >> 4) << 4));
    const uint32_t b_off = (uint32_t)((wc * 32 + (lane & 7) + ((lane >> 4) << 3)) * TILE_PITCH
                                      + (((lane >> 3) & 1) << 4));

    float acc[2][4][4];
    #pragma unroll
    for (int mt = 0; mt < 2; mt++)
        #pragma unroll
        for (int nt = 0; nt < 4; nt++)
            #pragma unroll
            for (int r = 0; r < 4; r++) acc[mt][nt][r] = 0.f;

    load_stage(0, 0);

    const int NK = D_ / 64;     // 16
    for (int kt = 0; kt < NK; kt++) {
        if (kt + 1 < NK) { load_stage((kt + 1) & 1, (kt + 1) * 64); CP_WAIT(1); }
        else             { CP_WAIT(0); }
        __syncthreads();

        uint32_t stage = sb + (kt & 1) * STAGE_B;
        #pragma unroll
        for (int kk = 0; kk < 4; kk++) {
            uint32_t ko = kk * 32;                  // 16 halves per k-step
            uint32_t ah[2][4];
            #pragma unroll
            for (int mt = 0; mt < 2; mt++)
                ldsm4(ah[mt], stage + a_off + mt * (16 * TILE_PITCH) + ko);
            uint32_t bh[2][4];
            #pragma unroll
            for (int ng = 0; ng < 2; ng++)
                ldsm4(bh[ng], stage + T_B0 + b_off + ng * (16 * TILE_PITCH) + ko);
            #pragma unroll
            for (int mt = 0; mt < 2; mt++)
                #pragma unroll
                for (int ng = 0; ng < 2; ng++)
                    #pragma unroll
                    for (int hf = 0; hf < 2; hf++)
                        mma16816(acc[mt][ng * 2 + hf], ah[mt], &bh[ng][hf * 2]);
        }
        __syncthreads();
    }

    // epilogue: fp16 everywhere; qk vs v routing per 8-col fragment
    #pragma unroll
    for (int mt = 0; mt < 2; mt++) {
        int rbase = row0 + wr * 32 + mt * 16 + (lane >> 2);
        #pragma unroll
        for (int nt = 0; nt < 4; nt++) {
            int colg = col0 + wc * 32 + nt * 8 + (lane & 3) * 2;
            uint32_t p0, p1;
            CVT2PKH(p0, acc[mt][nt][0], acc[mt][nt][1]);
            CVT2PKH(p1, acc[mt][nt][2], acc[mt][nt][3]);
            if (colg < QKW_) {
                *(uint32_t*)(g_qkh + (size_t)rbase * QKW_ + colg)       = p0;
                *(uint32_t*)(g_qkh + (size_t)(rbase + 8) * QKW_ + colg) = p1;
            } else {
                int col = colg - QKW_;
                *(uint32_t*)(g_vh + (size_t)rbase * D_ + col)       = p0;
                *(uint32_t*)(g_vh + (size_t)(rbase + 8) * D_ + col) = p1;
            }
        }
    }
}

// ---------------- L2 normalize + emit fp16 q (scaled), k --------------------
__global__ __launch_bounds__(256) void normalize_qk()
{
    int n = blockIdx.x;
    int b = n >> 11, nn = n & 2047;
    const __half* p = g_qkh + (size_t)n * QKW_;
    int t = threadIdx.x;
    float qv = __half2float(p[t]), kv = __half2float(p[RANK_ + t]);
    float qs = qv*qv, ks = kv*kv;
    #pragma unroll
    for (int o = 16; o; o >>= 1) {
        qs += __shfl_xor_sync(0xffffffffu, qs, o);
        ks += __shfl_xor_sync(0xffffffffu, ks, o);
    }
    __shared__ float sq[8], sk[8];
    if ((t & 31) == 0) { sq[t>>5] = qs; sk[t>>5] = ks; }
    __syncthreads();
    float qn = 0.f, kn = 0.f;
    #pragma unroll
    for (int w = 0; w < 8; w++) { qn += sq[w]; kn += sk[w]; }
    float qo = qv / fmaxf(sqrtf(qn), 1e-6f) * SCALE_;
    float ko = kv / fmaxf(sqrtf(kn), 1e-6f);

    int h = t >> 4, c = t & 15;
    size_t dst = ((size_t)(b*HEADS_ + h) * N_ + nn) * HS_ + c;
    g_q16[dst] = __float2half_rn(qo);
    g_k16[dst] = __float2half_rn(ko);
}

// ---------------- tensor-core causal flash attention ------------------------
// 128 threads / 64 q-rows per block, 4 warps, occ 4 (4 independent barrier
// groups per SM). Q,K,V,P fp16; lsum via P@ones MMA; mask only diagonal tile.
#define QT_ROWS 64
#define SQ_   0
#define SST_  3072
#define STG_  12288
#define SKH_  0
#define SVH_  3072
#define FLASH_SMEM 27648    // 3072 + 2*12288

__global__ __launch_bounds__(128, 4) void flash_tc(float* __restrict__ out)
{
    extern __shared__ __align__(128) char smem[];
    const uint32_t sb = smem_u32(smem);
    const int tid = threadIdx.x, lane = tid & 31, wid = tid >> 5;
    const int qt = gridDim.x - 1 - blockIdx.x;     // longest first
    const int h = blockIdx.y, b = blockIdx.z;
    const int q0 = qt * QT_ROWS;
    const size_t bh = (size_t)(b*HEADS_ + h) * N_;
    const size_t vb = (size_t)b * N_;

    {   // Q: 64 rows x 2 chunks = 128
        int row = tid >> 1, c = tid & 1;
        cp_async16(sb + SQ_ + row * 48 + c * 16,
                   g_q16 + (bh + q0 + row) * HS_ + c * 8);
    }
    CP_COMMIT();

    auto load_kv = [&](int s, int ktile) {
        uint32_t st = sb + SST_ + s * STG_;
        int j0 = ktile * 64;
        {   // K: 64 rows x 2 chunks = 128
            int c = tid & 1, row = tid >> 1;
            cp_async16(st + SKH_ + row * 48 + c * 16,
                       g_k16 + (bh + j0 + row) * HS_ + c * 8);
        }
        #pragma unroll
        for (int it = 0; it < 4; it++) {   // V: 64 rows x 8 chunks = 512
            int idx = tid + it * 128;
            int c = idx & 7, row = idx >> 3;
            cp_async16(st + SVH_ + row * 144 + c * 16,
                       g_vh + (vb + j0 + row) * D_ + h * DH_ + c * 8);
        }
        CP_COMMIT();
    };

    load_kv(0, 0);

    uint32_t qa[4];
    float yacc[8][4];
    #pragma unroll
    for (int nt = 0; nt < 8; nt++)
        #pragma unroll
        for (int r = 0; r < 4; r++) yacc[nt][r] = 0.f;
    float lacc[4] = {0.f, 0.f, 0.f, 0.f};          // P@ones accumulator
    const uint32_t ones2[2] = {0x3C003C00u, 0x3C003C00u};

    const int wmin = q0 + wid * 16;                // warp's min q row
    const int r0g = wmin + (lane >> 2);
    const int r1g = r0g + 8;
    const int nkt = qt + 1;
    const uint32_t qoff = (uint32_t)((wid * 16 + (lane & 15)) * 48 + ((lane >> 4) << 4));
    const uint32_t koff = (uint32_t)((((lane >> 4) << 3) + (lane & 7)) * 48
                                     + (((lane >> 3) & 1) << 4));
    const uint32_t voff = (uint32_t)(((((lane >> 3) & 1) << 3) + (lane & 7)) * 144
                                     + ((lane >> 4) << 4));

    for (int kt = 0; kt < nkt; kt++) {
        if (kt + 1 < nkt) { load_kv((kt + 1) & 1, kt + 1); CP_WAIT(1); }
        else              { CP_WAIT(0); }
        __syncthreads();

        if (kt == 0) ldsm4(qa, sb + SQ_ + qoff);

        const int j0 = kt * 64;
        uint32_t st = sb + SST_ + (kt & 1) * STG_;
        uint32_t pah[4][4];

        if (j0 + 63 <= wmin) {
            // ---- fast path: no masking anywhere in this tile ----
            #pragma unroll
            for (int ntp = 0; ntp < 4; ntp++) {
                uint32_t khr[4];
                ldsm4(khr, st + SKH_ + koff + ntp * (16 * 48));
                float s0[4] = {0,0,0,0}, s1[4] = {0,0,0,0};
                mma16816(s0, qa, &khr[0]);
                mma16816(s1, qa, &khr[2]);
                #pragma unroll
                for (int hf = 0; hf < 2; hf++) {
                    float* s = hf ? s1 : s0;
                    float p0 = exp_poly(s[0]), p1 = exp_poly(s[1]);
                    float p2 = exp_poly(s[2]), p3 = exp_poly(s[3]);
                    uint32_t hh01, hh23;
                    CVT2PKH(hh01, p0, p1);
                    CVT2PKH(hh23, p2, p3);
                    pah[ntp][hf * 2]     = hh01;
                    pah[ntp][hf * 2 + 1] = hh23;
                }
            }
        } else {
            // ---- diagonal tile: per-element causal mask ----
            #pragma unroll
            for (int ntp = 0; ntp < 4; ntp++) {
                uint32_t khr[4];
                ldsm4(khr, st + SKH_ + koff + ntp * (16 * 48));
                float s0[4] = {0,0,0,0}, s1[4] = {0,0,0,0};
                mma16816(s0, qa, &khr[0]);
                mma16816(s1, qa, &khr[2]);
                #pragma unroll
                for (int hf = 0; hf < 2; hf++) {
                    float* s = hf ? s1 : s0;
                    int c0 = j0 + (ntp * 2 + hf) * 8 + 2 * (lane & 3);
                    float p0 = (c0     <= r0g) ? exp_poly(s[0]) : 0.f;
                    float p1 = (c0 + 1 <= r0g) ? exp_poly(s[1]) : 0.f;
                    float p2 = (c0     <= r1g) ? exp_poly(s[2]) : 0.f;
                    float p3 = (c0 + 1 <= r1g) ? exp_poly(s[3]) : 0.f;
                    uint32_t hh01, hh23;
                    CVT2PKH(hh01, p0, p1);
                    CVT2PKH(hh23, p2, p3);
                    pah[ntp][hf * 2]     = hh01;
                    pah[ntp][hf * 2 + 1] = hh23;
                }
            }
        }

        // ---- lsum via P @ ones ----
        #pragma unroll
        for (int ks = 0; ks < 4; ks++)
            mma16816(lacc, pah[ks], ones2);

        // ---- P @ V ----
        #pragma unroll
        for (int ks = 0; ks < 4; ks++) {
            #pragma unroll
            for (int dnp = 0; dnp < 4; dnp++) {
                uint32_t vh4[4];
                ldsm4t(vh4, st + SVH_ + voff + ks * (16 * 144) + dnp * 32);
                mma16816(yacc[2*dnp],     pah[ks], &vh4[0]);
                mma16816(yacc[2*dnp + 1], pah[ks], &vh4[2]);
            }
        }
        __syncthreads();
    }

    // all-ones B makes every accumulator column the row sum: no shuffles needed
    float inv0 = 1.f / fmaxf(lacc[0], 1e-6f);
    float inv1 = 1.f / fmaxf(lacc[2], 1e-6f);

    float* o0 = out + ((size_t)b * N_ + r0g) * D_ + h * DH_ + 2 * (lane & 3);
    #pragma unroll
    for (int nt = 0; nt < 8; nt++) {
        *(float2*)(o0 + nt * 8)           = make_float2(yacc[nt][0] * inv0, yacc[nt][1] * inv0);
        *(float2*)(o0 + nt * 8 + 8 * D_)  = make_float2(yacc[nt][2] * inv1, yacc[nt][3] * inv1);
    }
}

// ----------------------------------------------------------------------------
extern "C" void kernel_launch(void* const* d_in, const int* in_sizes, int n_in,
                              void* d_out, int out_size)
{
    const float* x   = (const float*)d_in[0];
    const float* Wqk = (const float*)d_in[2];
    const float* Wv  = (const float*)d_in[3];
    float* out = (float*)d_out;

    __half *x16, *wh;
    cudaGetSymbolAddress((void**)&x16, g_x16);
    cudaGetSymbolAddress((void**)&wh, g_wh);

    cudaFuncSetAttribute(gemm_fused, cudaFuncAttributeMaxDynamicSharedMemorySize, GEMM_SMEM);
    cudaFuncSetAttribute(flash_tc,   cudaFuncAttributeMaxDynamicSharedMemorySize, FLASH_SMEM);

    convert_all<<<CVT_BLOCKS, 256>>>(x, Wqk, Wv);

    gemm_fused<<<dim3(CW_/NT_, MROWS/128), 384, GEMM_SMEM>>>(x16, wh);

    normalize_qk<<<MROWS, 256>>>();
    flash_tc<<<dim3(N_/QT_ROWS, HEADS_, B_), 128, FLASH_SMEM>>>(out);
}

// round 12
// speedup vs baseline: 1.1204x; 1.0512x over previous
#include <cuda_runtime.h>
#include <cuda_fp16.h>
#include <cstdint>
#include <math.h>

#define B_    2
#define N_    2048
#define D_    1024
#define RANK_ 256
#define HEADS_ 16
#define HS_   16
#define DH_   64
#define QKW_  512
#define CW_   1536           // merged GEMM output width (512 qk + 1024 v)
#define NT_   96             // GEMM N-tile
#define SCALE_ 0.25f
#define MROWS (B_*N_)        // 4096

// ---------------- device scratch (no allocation allowed) --------------------
__device__ __half g_qkh[MROWS*QKW_];      // fp16 qk pre-normalization
__device__ __half g_x16[MROWS*D_];        // x fp16
__device__ __half g_wh[CW_*D_];           // [Wqk;Wv] fp16
__device__ __half g_vh[MROWS*D_];         // v fp16
// q (scaled) and k fp16, [b,h,n,hs] layout
__device__ __half g_q16[B_*HEADS_*N_*HS_];
__device__ __half g_k16[B_*HEADS_*N_*HS_];

// ---------------- PTX helpers (sm_100-baseline safe) ------------------------
__device__ __forceinline__ uint32_t smem_u32(const void* p) {
    uint32_t a;
    asm("{ .reg .u64 t; cvta.to.shared.u64 t, %1; cvt.u32.u64 %0, t; }" : "=r"(a) : "l"(p));
    return a;
}
__device__ __forceinline__ void cp_async16(uint32_t dst, const void* src) {
    asm volatile("cp.async.cg.shared.global [%0], [%1], 16;" :: "r"(dst), "l"(src) : "memory");
}
#define CP_COMMIT() asm volatile("cp.async.commit_group;" ::: "memory")
#define CP_WAIT(n)  asm volatile("cp.async.wait_group %0;" :: "n"(n) : "memory")

__device__ __forceinline__ void ldsm4(uint32_t* r, uint32_t addr) {
    asm volatile("ldmatrix.sync.aligned.m8n8.x4.shared.b16 {%0,%1,%2,%3}, [%4];"
                 : "=r"(r[0]), "=r"(r[1]), "=r"(r[2]), "=r"(r[3]) : "r"(addr));
}
__device__ __forceinline__ void ldsm4t(uint32_t* r, uint32_t addr) {
    asm volatile("ldmatrix.sync.aligned.m8n8.x4.trans.shared.b16 {%0,%1,%2,%3}, [%4];"
                 : "=r"(r[0]), "=r"(r[1]), "=r"(r[2]), "=r"(r[3]) : "r"(addr));
}
__device__ __forceinline__ void mma16816(float* d, const uint32_t* a, const uint32_t* b) {
    asm volatile("mma.sync.aligned.m16n8k16.row.col.f32.f16.f16.f32 "
                 "{%0,%1,%2,%3}, {%4,%5,%6,%7}, {%8,%9}, {%0,%1,%2,%3};"
                 : "+f"(d[0]), "+f"(d[1]), "+f"(d[2]), "+f"(d[3])
                 : "r"(a[0]), "r"(a[1]), "r"(a[2]), "r"(a[3]), "r"(b[0]), "r"(b[1]));
}
// packed f32x2 -> f16x2 (lo arg in low half)
#define CVT2PKH(d, lo, hi) asm("cvt.rn.f16x2.f32 %0, %1, %2;" : "=r"(d) : "f"(hi), "f"(lo))

// exp(s) for |s| <= 0.26: Taylor-4 (fp32 path, used only on the diagonal tile)
__device__ __forceinline__ float exp_poly(float s) {
    float p = fmaf(s, 1.f/24.f, 1.f/6.f);
    p = fmaf(s, p, 0.5f);
    p = fmaf(s, p, 1.f);
    p = fmaf(s, p, 1.f);
    return p;
}

// ---------------- merged fp32 -> fp16 conversion (x, Wqk, Wv) ---------------
#define CVT_BLOCKS (4096 + 512 + 1024)
__global__ __launch_bounds__(256) void convert_all(const float* __restrict__ x,
                                                   const float* __restrict__ Wqk,
                                                   const float* __restrict__ Wv)
{
    int bid = blockIdx.x;
    const float* src;
    __half* dst;
    size_t off;
    if (bid < 4096)      { src = x;   dst = g_x16; off = (size_t)bid * 1024; }
    else if (bid < 4608) { src = Wqk; dst = g_wh;  off = (size_t)(bid - 4096) * 1024; }
    else                 { src = Wv;  dst = g_wh + (size_t)QKW_*D_; off = (size_t)(bid - 4608) * 1024; }
    size_t i = off + threadIdx.x * 4;
    float4 v = *(const float4*)(src + i);
    uint32_t h01, h23;
    CVT2PKH(h01, v.x, v.y);
    CVT2PKH(h23, v.z, v.w);
    *(uint2*)(dst + i) = make_uint2(h01, h23);
}

// ---------------- merged mma.sync fp16 GEMM ---------------------------------
#define TILE_PITCH 144                  // 64 halves + 16B pad
#define AT_B   (128 * TILE_PITCH)       // 18432
#define BT_B   (NT_ * TILE_PITCH)       // 13824
#define T_B0   AT_B
#define STAGE_B (AT_B + BT_B)           // 32256
#define GEMM_SMEM (2 * STAGE_B)         // 64512

__global__ __launch_bounds__(384, 2) void gemm_fused(const __half* __restrict__ A16,
                                                     const __half* __restrict__ Wh)
{
    extern __shared__ __align__(128) char smem[];
    const uint32_t sb = smem_u32(smem);

    const int tid = threadIdx.x;
    const int lane = tid & 31, wid = tid >> 5;
    const int wr = wid & 3, wc = wid >> 2;           // 4M x 3N warp grid
    const int row0 = blockIdx.y * 128, col0 = blockIdx.x * NT_;

    const __half* pA = A16 + (size_t)row0 * D_;
    const __half* pB = Wh + (size_t)col0 * D_;
    const int lrow = tid >> 3, lc = tid & 7;         // 48 rows per 384-thread pass

    auto load_stage = [&](int s, int k0) {
        uint32_t dbase = sb + s * STAGE_B;
        #pragma unroll
        for (int it = 0; it < 3; it++) {             // A: 128 rows x 8 chunks
            int row = lrow + it * 48;
            if (it < 2 || row < 128)
                cp_async16(dbase + row * TILE_PITCH + lc * 16,
                           pA + (size_t)row * D_ + k0 + lc * 8);
        }
        #pragma unroll
        for (int it = 0; it < 2; it++) {             // B: 96 rows x 8 chunks
            int row = lrow + it * 48;
            cp_async16(dbase + T_B0 + row * TILE_PITCH + lc * 16,
                       pB + (size_t)row * D_ + k0 + lc * 8);
        }
        CP_COMMIT();
    };

    const uint32_t a_off = (uint32_t)((wr * 32 + (lane & 15)) * TILE_PITCH + ((lane >> 4) << 4));
    const uint32_t b_off = (uint32_t)((wc * 32 + (lane & 7) + ((lane >> 4) << 3)) * TILE_PITCH
                                      + (((lane >> 3) & 1) << 4));

    float acc[2][4][4];
    #pragma unroll
    for (int mt = 0; mt < 2; mt++)
        #pragma unroll
        for (int nt = 0; nt < 4; nt++)
            #pragma unroll
            for (int r = 0; r < 4; r++) acc[mt][nt][r] = 0.f;

    load_stage(0, 0);

    const int NK = D_ / 64;     // 16
    for (int kt = 0; kt < NK; kt++) {
        if (kt + 1 < NK) { load_stage((kt + 1) & 1, (kt + 1) * 64); CP_WAIT(1); }
        else             { CP_WAIT(0); }
        __syncthreads();

        uint32_t stage = sb + (kt & 1) * STAGE_B;
        #pragma unroll
        for (int kk = 0; kk < 4; kk++) {
            uint32_t ko = kk * 32;                  // 16 halves per k-step
            uint32_t ah[2][4];
            #pragma unroll
            for (int mt = 0; mt < 2; mt++)
                ldsm4(ah[mt], stage + a_off + mt * (16 * TILE_PITCH) + ko);
            uint32_t bh[2][4];
            #pragma unroll
            for (int ng = 0; ng < 2; ng++)
                ldsm4(bh[ng], stage + T_B0 + b_off + ng * (16 * TILE_PITCH) + ko);
            #pragma unroll
            for (int mt = 0; mt < 2; mt++)
                #pragma unroll
                for (int ng = 0; ng < 2; ng++)
                    #pragma unroll
                    for (int hf = 0; hf < 2; hf++)
                        mma16816(acc[mt][ng * 2 + hf], ah[mt], &bh[ng][hf * 2]);
        }
        __syncthreads();
    }

    // epilogue: fp16 everywhere; qk vs v routing per 8-col fragment
    #pragma unroll
    for (int mt = 0; mt < 2; mt++) {
        int rbase = row0 + wr * 32 + mt * 16 + (lane >> 2);
        #pragma unroll
        for (int nt = 0; nt < 4; nt++) {
            int colg = col0 + wc * 32 + nt * 8 + (lane & 3) * 2;
            uint32_t p0, p1;
            CVT2PKH(p0, acc[mt][nt][0], acc[mt][nt][1]);
            CVT2PKH(p1, acc[mt][nt][2], acc[mt][nt][3]);
            if (colg < QKW_) {
                *(uint32_t*)(g_qkh + (size_t)rbase * QKW_ + colg)       = p0;
                *(uint32_t*)(g_qkh + (size_t)(rbase + 8) * QKW_ + colg) = p1;
            } else {
                int col = colg - QKW_;
                *(uint32_t*)(g_vh + (size_t)rbase * D_ + col)       = p0;
                *(uint32_t*)(g_vh + (size_t)(rbase + 8) * D_ + col) = p1;
            }
        }
    }
}

// ---------------- L2 normalize + emit fp16 q (scaled), k --------------------
__global__ __launch_bounds__(256) void normalize_qk()
{
    int n = blockIdx.x;
    int b = n >> 11, nn = n & 2047;
    const __half* p = g_qkh + (size_t)n * QKW_;
    int t = threadIdx.x;
    float qv = __half2float(p[t]), kv = __half2float(p[RANK_ + t]);
    float qs = qv*qv, ks = kv*kv;
    #pragma unroll
    for (int o = 16; o; o >>= 1) {
        qs += __shfl_xor_sync(0xffffffffu, qs, o);
        ks += __shfl_xor_sync(0xffffffffu, ks, o);
    }
    __shared__ float sq[8], sk[8];
    if ((t & 31) == 0) { sq[t>>5] = qs; sk[t>>5] = ks; }
    __syncthreads();
    float qn = 0.f, kn = 0.f;
    #pragma unroll
    for (int w = 0; w < 8; w++) { qn += sq[w]; kn += sk[w]; }
    float qo = qv / fmaxf(sqrtf(qn), 1e-6f) * SCALE_;
    float ko = kv / fmaxf(sqrtf(kn), 1e-6f);

    int h = t >> 4, c = t & 15;
    size_t dst = ((size_t)(b*HEADS_ + h) * N_ + nn) * HS_ + c;
    g_q16[dst] = __float2half_rn(qo);
    g_k16[dst] = __float2half_rn(ko);
}

// ---------------- tensor-core causal flash attention ------------------------
// 128 threads / 64 q-rows, occ 5. exp via packed HFMA2 on non-diagonal tiles.
#define QT_ROWS 64
#define SQ_   0
#define SST_  3072
#define STG_  12288
#define SKH_  0
#define SVH_  3072
#define FLASH_SMEM 27648    // 3072 + 2*12288

__global__ __launch_bounds__(128, 5) void flash_tc(float* __restrict__ out)
{
    extern __shared__ __align__(128) char smem[];
    const uint32_t sb = smem_u32(smem);
    const int tid = threadIdx.x, lane = tid & 31, wid = tid >> 5;
    const int qt = gridDim.x - 1 - blockIdx.x;     // longest first
    const int h = blockIdx.y, b = blockIdx.z;
    const int q0 = qt * QT_ROWS;
    const size_t bh = (size_t)(b*HEADS_ + h) * N_;
    const size_t vb = (size_t)b * N_;

    {   // Q: 64 rows x 2 chunks = 128
        int row = tid >> 1, c = tid & 1;
        cp_async16(sb + SQ_ + row * 48 + c * 16,
                   g_q16 + (bh + q0 + row) * HS_ + c * 8);
    }
    CP_COMMIT();

    auto load_kv = [&](int s, int ktile) {
        uint32_t st = sb + SST_ + s * STG_;
        int j0 = ktile * 64;
        {   // K: 64 rows x 2 chunks = 128
            int c = tid & 1, row = tid >> 1;
            cp_async16(st + SKH_ + row * 48 + c * 16,
                       g_k16 + (bh + j0 + row) * HS_ + c * 8);
        }
        #pragma unroll
        for (int it = 0; it < 4; it++) {   // V: 64 rows x 8 chunks = 512
            int idx = tid + it * 128;
            int c = idx & 7, row = idx >> 3;
            cp_async16(st + SVH_ + row * 144 + c * 16,
                       g_vh + (vb + j0 + row) * D_ + h * DH_ + c * 8);
        }
        CP_COMMIT();
    };

    load_kv(0, 0);

    uint32_t qa[4];
    float yacc[8][4];
    #pragma unroll
    for (int nt = 0; nt < 8; nt++)
        #pragma unroll
        for (int r = 0; r < 4; r++) yacc[nt][r] = 0.f;
    float lacc[4] = {0.f, 0.f, 0.f, 0.f};          // P@ones accumulator
    const uint32_t ones2[2] = {0x3C003C00u, 0x3C003C00u};

    // h2 Taylor-4 coefficients
    const __half2 C4 = __float2half2_rn(1.f/24.f);
    const __half2 C3 = __float2half2_rn(1.f/6.f);
    const __half2 C2 = __float2half2_rn(0.5f);
    const __half2 C1 = __float2half2_rn(1.f);

    const int wmin = q0 + wid * 16;                // warp's min q row
    const int r0g = wmin + (lane >> 2);
    const int r1g = r0g + 8;
    const int nkt = qt + 1;
    const uint32_t qoff = (uint32_t)((wid * 16 + (lane & 15)) * 48 + ((lane >> 4) << 4));
    const uint32_t koff = (uint32_t)((((lane >> 4) << 3) + (lane & 7)) * 48
                                     + (((lane >> 3) & 1) << 4));
    const uint32_t voff = (uint32_t)(((((lane >> 3) & 1) << 3) + (lane & 7)) * 144
                                     + ((lane >> 4) << 4));

    for (int kt = 0; kt < nkt; kt++) {
        if (kt + 1 < nkt) { load_kv((kt + 1) & 1, kt + 1); CP_WAIT(1); }
        else              { CP_WAIT(0); }
        __syncthreads();

        if (kt == 0) ldsm4(qa, sb + SQ_ + qoff);

        const int j0 = kt * 64;
        uint32_t st = sb + SST_ + (kt & 1) * STG_;
        uint32_t pah[4][4];

        if (j0 + 63 <= wmin) {
            // ---- fast path: no masking; exp via packed HFMA2 ----
            #pragma unroll
            for (int ntp = 0; ntp < 4; ntp++) {
                uint32_t khr[4];
                ldsm4(khr, st + SKH_ + koff + ntp * (16 * 48));
                float s0[4] = {0,0,0,0}, s1[4] = {0,0,0,0};
                mma16816(s0, qa, &khr[0]);
                mma16816(s1, qa, &khr[2]);
                #pragma unroll
                for (int hf = 0; hf < 2; hf++) {
                    float* s = hf ? s1 : s0;
                    uint32_t sa, sbp;
                    CVT2PKH(sa,  s[0], s[1]);
                    CVT2PKH(sbp, s[2], s[3]);
                    __half2 va = *(__half2*)&sa, vb2 = *(__half2*)&sbp;
                    __half2 pa = __hfma2(va, C4, C3);
                    __half2 pb = __hfma2(vb2, C4, C3);
                    pa = __hfma2(va, pa, C2);  pb = __hfma2(vb2, pb, C2);
                    pa = __hfma2(va, pa, C1);  pb = __hfma2(vb2, pb, C1);
                    pa = __hfma2(va, pa, C1);  pb = __hfma2(vb2, pb, C1);
                    pah[ntp][hf * 2]     = *(uint32_t*)&pa;
                    pah[ntp][hf * 2 + 1] = *(uint32_t*)&pb;
                }
            }
        } else {
            // ---- diagonal tile: per-element causal mask (fp32 path) ----
            #pragma unroll
            for (int ntp = 0; ntp < 4; ntp++) {
                uint32_t khr[4];
                ldsm4(khr, st + SKH_ + koff + ntp * (16 * 48));
                float s0[4] = {0,0,0,0}, s1[4] = {0,0,0,0};
                mma16816(s0, qa, &khr[0]);
                mma16816(s1, qa, &khr[2]);
                #pragma unroll
                for (int hf = 0; hf < 2; hf++) {
                    float* s = hf ? s1 : s0;
                    int c0 = j0 + (ntp * 2 + hf) * 8 + 2 * (lane & 3);
                    float p0 = (c0     <= r0g) ? exp_poly(s[0]) : 0.f;
                    float p1 = (c0 + 1 <= r0g) ? exp_poly(s[1]) : 0.f;
                    float p2 = (c0     <= r1g) ? exp_poly(s[2]) : 0.f;
                    float p3 = (c0 + 1 <= r1g) ? exp_poly(s[3]) : 0.f;
                    uint32_t hh01, hh23;
                    CVT2PKH(hh01, p0, p1);
                    CVT2PKH(hh23, p2, p3);
                    pah[ntp][hf * 2]     = hh01;
                    pah[ntp][hf * 2 + 1] = hh23;
                }
            }
        }

        // ---- lsum via P @ ones ----
        #pragma unroll
        for (int ks = 0; ks < 4; ks++)
            mma16816(lacc, pah[ks], ones2);

        // ---- P @ V ----
        #pragma unroll
        for (int ks = 0; ks < 4; ks++) {
            #pragma unroll
            for (int dnp = 0; dnp < 4; dnp++) {
                uint32_t vh4[4];
                ldsm4t(vh4, st + SVH_ + voff + ks * (16 * 144) + dnp * 32);
                mma16816(yacc[2*dnp],     pah[ks], &vh4[0]);
                mma16816(yacc[2*dnp + 1], pah[ks], &vh4[2]);
            }
        }
        __syncthreads();
    }

    // all-ones B makes every accumulator column the row sum: no shuffles needed
    float inv0 = 1.f / fmaxf(lacc[0], 1e-6f);
    float inv1 = 1.f / fmaxf(lacc[2], 1e-6f);

    float* o0 = out + ((size_t)b * N_ + r0g) * D_ + h * DH_ + 2 * (lane & 3);
    #pragma unroll
    for (int nt = 0; nt < 8; nt++) {
        *(float2*)(o0 + nt * 8)           = make_float2(yacc[nt][0] * inv0, yacc[nt][1] * inv0);
        *(float2*)(o0 + nt * 8 + 8 * D_)  = make_float2(yacc[nt][2] * inv1, yacc[nt][3] * inv1);
    }
}

// ----------------------------------------------------------------------------
extern "C" void kernel_launch(void* const* d_in, const int* in_sizes, int n_in,
                              void* d_out, int out_size)
{
    const float* x   = (const float*)d_in[0];
    const float* Wqk = (const float*)d_in[2];
    const float* Wv  = (const float*)d_in[3];
    float* out = (float*)d_out;

    __half *x16, *wh;
    cudaGetSymbolAddress((void**)&x16, g_x16);
    cudaGetSymbolAddress((void**)&wh, g_wh);

    cudaFuncSetAttribute(gemm_fused, cudaFuncAttributeMaxDynamicSharedMemorySize, GEMM_SMEM);
    cudaFuncSetAttribute(flash_tc,   cudaFuncAttributeMaxDynamicSharedMemorySize, FLASH_SMEM);

    convert_all<<<CVT_BLOCKS, 256>>>(x, Wqk, Wv);

    gemm_fused<<<dim3(CW_/NT_, MROWS/128), 384, GEMM_SMEM>>>(x16, wh);

    normalize_qk<<<MROWS, 256>>>();
    flash_tc<<<dim3(N_/QT_ROWS, HEADS_, B_), 128, FLASH_SMEM>>>(out);
}

// round 13
// speedup vs baseline: 1.1600x; 1.0354x over previous
#include <cuda_runtime.h>
#include <cuda_fp16.h>
#include <cstdint>
#include <math.h>

#define B_    2
#define N_    2048
#define D_    1024
#define RANK_ 256
#define HEADS_ 16
#define HS_   16
#define DH_   64
#define QKW_  512
#define CW_   1536           // merged GEMM output width (512 qk + 1024 v)
#define NT_   96             // GEMM N-tile
#define SCALE_ 0.25f
#define MROWS (B_*N_)        // 4096

// ---------------- device scratch (no allocation allowed) --------------------
__device__ __half g_qkh[MROWS*QKW_];      // fp16 qk pre-normalization
__device__ __half g_x16[MROWS*D_];        // x fp16
__device__ __half g_wh[CW_*D_];           // [Wqk;Wv] fp16
__device__ __half g_vh[MROWS*D_];         // v fp16
// q (scaled) and k fp16, [b,h,n,hs] layout
__device__ __half g_q16[B_*HEADS_*N_*HS_];
__device__ __half g_k16[B_*HEADS_*N_*HS_];

// ---------------- PTX helpers (sm_100-baseline safe) ------------------------
__device__ __forceinline__ uint32_t smem_u32(const void* p) {
    uint32_t a;
    asm("{ .reg .u64 t; cvta.to.shared.u64 t, %1; cvt.u32.u64 %0, t; }" : "=r"(a) : "l"(p));
    return a;
}
__device__ __forceinline__ void cp_async16(uint32_t dst, const void* src) {
    asm volatile("cp.async.cg.shared.global [%0], [%1], 16;" :: "r"(dst), "l"(src) : "memory");
}
#define CP_COMMIT() asm volatile("cp.async.commit_group;" ::: "memory")
#define CP_WAIT(n)  asm volatile("cp.async.wait_group %0;" :: "n"(n) : "memory")

__device__ __forceinline__ void ldsm4(uint32_t* r, uint32_t addr) {
    asm volatile("ldmatrix.sync.aligned.m8n8.x4.shared.b16 {%0,%1,%2,%3}, [%4];"
                 : "=r"(r[0]), "=r"(r[1]), "=r"(r[2]), "=r"(r[3]) : "r"(addr));
}
__device__ __forceinline__ void ldsm4t(uint32_t* r, uint32_t addr) {
    asm volatile("ldmatrix.sync.aligned.m8n8.x4.trans.shared.b16 {%0,%1,%2,%3}, [%4];"
                 : "=r"(r[0]), "=r"(r[1]), "=r"(r[2]), "=r"(r[3]) : "r"(addr));
}
__device__ __forceinline__ void mma16816(float* d, const uint32_t* a, const uint32_t* b) {
    asm volatile("mma.sync.aligned.m16n8k16.row.col.f32.f16.f16.f32 "
                 "{%0,%1,%2,%3}, {%4,%5,%6,%7}, {%8,%9}, {%0,%1,%2,%3};"
                 : "+f"(d[0]), "+f"(d[1]), "+f"(d[2]), "+f"(d[3])
                 : "r"(a[0]), "r"(a[1]), "r"(a[2]), "r"(a[3]), "r"(b[0]), "r"(b[1]));
}
// packed f32x2 -> f16x2 (lo arg in low half)
#define CVT2PKH(d, lo, hi) asm("cvt.rn.f16x2.f32 %0, %1, %2;" : "=r"(d) : "f"(hi), "f"(lo))

// exp(s) for |s| <= 0.26: Taylor-4 (fp32 path, used only on the diagonal tile)
__device__ __forceinline__ float exp_poly(float s) {
    float p = fmaf(s, 1.f/24.f, 1.f/6.f);
    p = fmaf(s, p, 0.5f);
    p = fmaf(s, p, 1.f);
    p = fmaf(s, p, 1.f);
    return p;
}

// ---------------- merged fp32 -> fp16 conversion (x, Wqk, Wv) ---------------
#define CVT_BLOCKS (4096 + 512 + 1024)
__global__ __launch_bounds__(256) void convert_all(const float* __restrict__ x,
                                                   const float* __restrict__ Wqk,
                                                   const float* __restrict__ Wv)
{
    int bid = blockIdx.x;
    const float* src;
    __half* dst;
    size_t off;
    if (bid < 4096)      { src = x;   dst = g_x16; off = (size_t)bid * 1024; }
    else if (bid < 4608) { src = Wqk; dst = g_wh;  off = (size_t)(bid - 4096) * 1024; }
    else                 { src = Wv;  dst = g_wh + (size_t)QKW_*D_; off = (size_t)(bid - 4608) * 1024; }
    size_t i = off + threadIdx.x * 4;
    float4 v = *(const float4*)(src + i);
    uint32_t h01, h23;
    CVT2PKH(h01, v.x, v.y);
    CVT2PKH(h23, v.z, v.w);
    *(uint2*)(dst + i) = make_uint2(h01, h23);
}

// ---------------- merged mma.sync fp16 GEMM (3-stage pipeline) ---------------
#define TILE_PITCH 144                  // 64 halves + 16B pad
#define AT_B   (128 * TILE_PITCH)       // 18432
#define BT_B   (NT_ * TILE_PITCH)       // 13824
#define T_B0   AT_B
#define STAGE_B (AT_B + BT_B)           // 32256
#define GEMM_SMEM (3 * STAGE_B)         // 96768

__global__ __launch_bounds__(384, 2) void gemm_fused(const __half* __restrict__ A16,
                                                     const __half* __restrict__ Wh)
{
    extern __shared__ __align__(128) char smem[];
    const uint32_t sb = smem_u32(smem);

    const int tid = threadIdx.x;
    const int lane = tid & 31, wid = tid >> 5;
    const int wr = wid & 3, wc = wid >> 2;           // 4M x 3N warp grid
    const int row0 = blockIdx.y * 128, col0 = blockIdx.x * NT_;

    const __half* pA = A16 + (size_t)row0 * D_;
    const __half* pB = Wh + (size_t)col0 * D_;
    const int lrow = tid >> 3, lc = tid & 7;         // 48 rows per 384-thread pass

    auto load_stage = [&](int s, int k0) {
        uint32_t dbase = sb + s * STAGE_B;
        #pragma unroll
        for (int it = 0; it < 3; it++) {             // A: 128 rows x 8 chunks
            int row = lrow + it * 48;
            if (it < 2 || row < 128)
                cp_async16(dbase + row * TILE_PITCH + lc * 16,
                           pA + (size_t)row * D_ + k0 + lc * 8);
        }
        #pragma unroll
        for (int it = 0; it < 2; it++) {             // B: 96 rows x 8 chunks
            int row = lrow + it * 48;
            cp_async16(dbase + T_B0 + row * TILE_PITCH + lc * 16,
                       pB + (size_t)row * D_ + k0 + lc * 8);
        }
        CP_COMMIT();
    };

    const uint32_t a_off = (uint32_t)((wr * 32 + (lane & 15)) * TILE_PITCH + ((lane >> 4) << 4));
    const uint32_t b_off = (uint32_t)((wc * 32 + (lane & 7) + ((lane >> 4) << 3)) * TILE_PITCH
                                      + (((lane >> 3) & 1) << 4));

    float acc[2][4][4];
    #pragma unroll
    for (int mt = 0; mt < 2; mt++)
        #pragma unroll
        for (int nt = 0; nt < 4; nt++)
            #pragma unroll
            for (int r = 0; r < 4; r++) acc[mt][nt][r] = 0.f;

    load_stage(0, 0);

    const int NK = D_ / 64;     // 16
    int s_cur = 0, s_nxt = 1;
    for (int kt = 0; kt < NK; kt++) {
        if (kt + 1 < NK) { load_stage(s_nxt, (kt + 1) * 64); CP_WAIT(1); }
        else             { CP_WAIT(0); }
        __syncthreads();        // kt's loads visible; overwritten stage was read at kt-2

        uint32_t stage = sb + s_cur * STAGE_B;
        #pragma unroll
        for (int kk = 0; kk < 4; kk++) {
            uint32_t ko = kk * 32;                  // 16 halves per k-step
            uint32_t ah[2][4];
            #pragma unroll
            for (int mt = 0; mt < 2; mt++)
                ldsm4(ah[mt], stage + a_off + mt * (16 * TILE_PITCH) + ko);
            uint32_t bh[2][4];
            #pragma unroll
            for (int ng = 0; ng < 2; ng++)
                ldsm4(bh[ng], stage + T_B0 + b_off + ng * (16 * TILE_PITCH) + ko);
            #pragma unroll
            for (int mt = 0; mt < 2; mt++)
                #pragma unroll
                for (int ng = 0; ng < 2; ng++)
                    #pragma unroll
                    for (int hf = 0; hf < 2; hf++)
                        mma16816(acc[mt][ng * 2 + hf], ah[mt], &bh[ng][hf * 2]);
        }
        s_cur = s_nxt;
        s_nxt = (s_nxt == 2) ? 0 : s_nxt + 1;
    }

    // epilogue: fp16 everywhere; qk vs v routing per 8-col fragment
    #pragma unroll
    for (int mt = 0; mt < 2; mt++) {
        int rbase = row0 + wr * 32 + mt * 16 + (lane >> 2);
        #pragma unroll
        for (int nt = 0; nt < 4; nt++) {
            int colg = col0 + wc * 32 + nt * 8 + (lane & 3) * 2;
            uint32_t p0, p1;
            CVT2PKH(p0, acc[mt][nt][0], acc[mt][nt][1]);
            CVT2PKH(p1, acc[mt][nt][2], acc[mt][nt][3]);
            if (colg < QKW_) {
                *(uint32_t*)(g_qkh + (size_t)rbase * QKW_ + colg)       = p0;
                *(uint32_t*)(g_qkh + (size_t)(rbase + 8) * QKW_ + colg) = p1;
            } else {
                int col = colg - QKW_;
                *(uint32_t*)(g_vh + (size_t)rbase * D_ + col)       = p0;
                *(uint32_t*)(g_vh + (size_t)(rbase + 8) * D_ + col) = p1;
            }
        }
    }
}

// ---------------- L2 normalize + emit fp16 q (scaled), k --------------------
__global__ __launch_bounds__(256) void normalize_qk()
{
    int n = blockIdx.x;
    int b = n >> 11, nn = n & 2047;
    const __half* p = g_qkh + (size_t)n * QKW_;
    int t = threadIdx.x;
    float qv = __half2float(p[t]), kv = __half2float(p[RANK_ + t]);
    float qs = qv*qv, ks = kv*kv;
    #pragma unroll
    for (int o = 16; o; o >>= 1) {
        qs += __shfl_xor_sync(0xffffffffu, qs, o);
        ks += __shfl_xor_sync(0xffffffffu, ks, o);
    }
    __shared__ float sq[8], sk[8];
    if ((t & 31) == 0) { sq[t>>5] = qs; sk[t>>5] = ks; }
    __syncthreads();
    float qn = 0.f, kn = 0.f;
    #pragma unroll
    for (int w = 0; w < 8; w++) { qn += sq[w]; kn += sk[w]; }
    float qo = qv / fmaxf(sqrtf(qn), 1e-6f) * SCALE_;
    float ko = kv / fmaxf(sqrtf(kn), 1e-6f);

    int h = t >> 4, c = t & 15;
    size_t dst = ((size_t)(b*HEADS_ + h) * N_ + nn) * HS_ + c;
    g_q16[dst] = __float2half_rn(qo);
    g_k16[dst] = __float2half_rn(ko);
}

// ---------------- tensor-core causal flash attention ------------------------
// 128 threads / 64 q-rows, occ 5, 3-stage KV pipeline, ONE barrier/iter.
#define QT_ROWS 64
#define SQ_   0
#define SST_  3072
#define STG_  12288
#define SKH_  0
#define SVH_  3072
#define FLASH_SMEM (3072 + 3*12288)   // 39936

__global__ __launch_bounds__(128, 5) void flash_tc(float* __restrict__ out)
{
    extern __shared__ __align__(128) char smem[];
    const uint32_t sb = smem_u32(smem);
    const int tid = threadIdx.x, lane = tid & 31, wid = tid >> 5;
    const int qt = gridDim.x - 1 - blockIdx.x;     // longest first
    const int h = blockIdx.y, b = blockIdx.z;
    const int q0 = qt * QT_ROWS;
    const size_t bh = (size_t)(b*HEADS_ + h) * N_;
    const size_t vb = (size_t)b * N_;

    {   // Q: 64 rows x 2 chunks = 128  (commit group 0)
        int row = tid >> 1, c = tid & 1;
        cp_async16(sb + SQ_ + row * 48 + c * 16,
                   g_q16 + (bh + q0 + row) * HS_ + c * 8);
    }
    CP_COMMIT();

    auto load_kv = [&](int s, int ktile) {
        uint32_t st = sb + SST_ + s * STG_;
        int j0 = ktile * 64;
        {   // K: 64 rows x 2 chunks = 128
            int c = tid & 1, row = tid >> 1;
            cp_async16(st + SKH_ + row * 48 + c * 16,
                       g_k16 + (bh + j0 + row) * HS_ + c * 8);
        }
        #pragma unroll
        for (int it = 0; it < 4; it++) {   // V: 64 rows x 8 chunks = 512
            int idx = tid + it * 128;
            int c = idx & 7, row = idx >> 3;
            cp_async16(st + SVH_ + row * 144 + c * 16,
                       g_vh + (vb + j0 + row) * D_ + h * DH_ + c * 8);
        }
        CP_COMMIT();
    };

    load_kv(0, 0);

    uint32_t qa[4];
    float yacc[8][4];
    #pragma unroll
    for (int nt = 0; nt < 8; nt++)
        #pragma unroll
        for (int r = 0; r < 4; r++) yacc[nt][r] = 0.f;
    float lacc[4] = {0.f, 0.f, 0.f, 0.f};          // P@ones accumulator
    const uint32_t ones2[2] = {0x3C003C00u, 0x3C003C00u};

    // h2 Taylor-4 coefficients
    const __half2 C4 = __float2half2_rn(1.f/24.f);
    const __half2 C3 = __float2half2_rn(1.f/6.f);
    const __half2 C2 = __float2half2_rn(0.5f);
    const __half2 C1 = __float2half2_rn(1.f);

    const int wmin = q0 + wid * 16;                // warp's min q row
    const int r0g = wmin + (lane >> 2);
    const int r1g = r0g + 8;
    const int nkt = qt + 1;
    const uint32_t qoff = (uint32_t)((wid * 16 + (lane & 15)) * 48 + ((lane >> 4) << 4));
    const uint32_t koff = (uint32_t)((((lane >> 4) << 3) + (lane & 7)) * 48
                                     + (((lane >> 3) & 1) << 4));
    const uint32_t voff = (uint32_t)(((((lane >> 3) & 1) << 3) + (lane & 7)) * 144
                                     + ((lane >> 4) << 4));

    int s_cur = 0, s_nxt = 1;
    for (int kt = 0; kt < nkt; kt++) {
        if (kt + 1 < nkt) { load_kv(s_nxt, kt + 1); CP_WAIT(1); }
        else              { CP_WAIT(0); }
        __syncthreads();        // kt visible; overwritten stage was read at kt-2

        if (kt == 0) ldsm4(qa, sb + SQ_ + qoff);

        const int j0 = kt * 64;
        uint32_t st = sb + SST_ + s_cur * STG_;
        uint32_t pah[4][4];

        if (j0 + 63 <= wmin) {
            // ---- fast path: no masking; exp via packed HFMA2 ----
            #pragma unroll
            for (int ntp = 0; ntp < 4; ntp++) {
                uint32_t khr[4];
                ldsm4(khr, st + SKH_ + koff + ntp * (16 * 48));
                float s0[4] = {0,0,0,0}, s1[4] = {0,0,0,0};
                mma16816(s0, qa, &khr[0]);
                mma16816(s1, qa, &khr[2]);
                #pragma unroll
                for (int hf = 0; hf < 2; hf++) {
                    float* s = hf ? s1 : s0;
                    uint32_t sa, sbp;
                    CVT2PKH(sa,  s[0], s[1]);
                    CVT2PKH(sbp, s[2], s[3]);
                    __half2 va = *(__half2*)&sa, vb2 = *(__half2*)&sbp;
                    __half2 pa = __hfma2(va, C4, C3);
                    __half2 pb = __hfma2(vb2, C4, C3);
                    pa = __hfma2(va, pa, C2);  pb = __hfma2(vb2, pb, C2);
                    pa = __hfma2(va, pa, C1);  pb = __hfma2(vb2, pb, C1);
                    pa = __hfma2(va, pa, C1);  pb = __hfma2(vb2, pb, C1);
                    pah[ntp][hf * 2]     = *(uint32_t*)&pa;
                    pah[ntp][hf * 2 + 1] = *(uint32_t*)&pb;
                }
            }
        } else {
            // ---- diagonal tile: per-element causal mask (fp32 path) ----
            #pragma unroll
            for (int ntp = 0; ntp < 4; ntp++) {
                uint32_t khr[4];
                ldsm4(khr, st + SKH_ + koff + ntp * (16 * 48));
                float s0[4] = {0,0,0,0}, s1[4] = {0,0,0,0};
                mma16816(s0, qa, &khr[0]);
                mma16816(s1, qa, &khr[2]);
                #pragma unroll
                for (int hf = 0; hf < 2; hf++) {
                    float* s = hf ? s1 : s0;
                    int c0 = j0 + (ntp * 2 + hf) * 8 + 2 * (lane & 3);
                    float p0 = (c0     <= r0g) ? exp_poly(s[0]) : 0.f;
                    float p1 = (c0 + 1 <= r0g) ? exp_poly(s[1]) : 0.f;
                    float p2 = (c0     <= r1g) ? exp_poly(s[2]) : 0.f;
                    float p3 = (c0 + 1 <= r1g) ? exp_poly(s[3]) : 0.f;
                    uint32_t hh01, hh23;
                    CVT2PKH(hh01, p0, p1);
                    CVT2PKH(hh23, p2, p3);
                    pah[ntp][hf * 2]     = hh01;
                    pah[ntp][hf * 2 + 1] = hh23;
                }
            }
        }

        // ---- lsum via P @ ones ----
        #pragma unroll
        for (int ks = 0; ks < 4; ks++)
            mma16816(lacc, pah[ks], ones2);

        // ---- P @ V ----
        #pragma unroll
        for (int ks = 0; ks < 4; ks++) {
            #pragma unroll
            for (int dnp = 0; dnp < 4; dnp++) {
                uint32_t vh4[4];
                ldsm4t(vh4, st + SVH_ + voff + ks * (16 * 144) + dnp * 32);
                mma16816(yacc[2*dnp],     pah[ks], &vh4[0]);
                mma16816(yacc[2*dnp + 1], pah[ks], &vh4[2]);
            }
        }
        s_cur = s_nxt;
        s_nxt = (s_nxt == 2) ? 0 : s_nxt + 1;
    }

    // all-ones B makes every accumulator column the row sum: no shuffles needed
    float inv0 = 1.f / fmaxf(lacc[0], 1e-6f);
    float inv1 = 1.f / fmaxf(lacc[2], 1e-6f);

    float* o0 = out + ((size_t)b * N_ + r0g) * D_ + h * DH_ + 2 * (lane & 3);
    #pragma unroll
    for (int nt = 0; nt < 8; nt++) {
        *(float2*)(o0 + nt * 8)           = make_float2(yacc[nt][0] * inv0, yacc[nt][1] * inv0);
        *(float2*)(o0 + nt * 8 + 8 * D_)  = make_float2(yacc[nt][2] * inv1, yacc[nt][3] * inv1);
    }
}

// ----------------------------------------------------------------------------
extern "C" void kernel_launch(void* const* d_in, const int* in_sizes, int n_in,
                              void* d_out, int out_size)
{
    const float* x   = (const float*)d_in[0];
    const float* Wqk = (const float*)d_in[2];
    const float* Wv  = (const float*)d_in[3];
    float* out = (float*)d_out;

    __half *x16, *wh;
    cudaGetSymbolAddress((void**)&x16, g_x16);
    cudaGetSymbolAddress((void**)&wh, g_wh);

    cudaFuncSetAttribute(gemm_fused, cudaFuncAttributeMaxDynamicSharedMemorySize, GEMM_SMEM);
    cudaFuncSetAttribute(flash_tc,   cudaFuncAttributeMaxDynamicSharedMemorySize, FLASH_SMEM);

    convert_all<<<CVT_BLOCKS, 256>>>(x, Wqk, Wv);

    gemm_fused<<<dim3(CW_/NT_, MROWS/128), 384, GEMM_SMEM>>>(x16, wh);

    normalize_qk<<<MROWS, 256>>>();
    flash_tc<<<dim3(N_/QT_ROWS, HEADS_, B_), 128, FLASH_SMEM>>>(out);
}